// round 6
// baseline (speedup 1.0000x reference)
#include <cuda_runtime.h>
#include <math.h>
#include <stdint.h>

#define D_MODEL 768
#define N_HEADS 12
#define D_HEAD  64
#define BATCH   2
#define SEQ     2048
#define BT      (BATCH*SEQ)            // 4096
#define QKV_N   (3*N_HEADS*D_HEAD)     // 2304
#define BH      (BATCH*N_HEADS)        // 24

#define X_ELEMS  (BATCH*SEQ*D_MODEL)           // 3145728 (unique)
#define W_ELEMS  (N_HEADS*D_MODEL*D_HEAD)      // 589824  (x4)
#define B_ELEMS  (D_MODEL)                     // 768     (x4)

// ---------------- scratch (static device globals; no allocation allowed) ----
__device__ float g_Wpack[(size_t)D_MODEL * QKV_N];          // [c][n]   7.1 MB
__device__ float g_bpack[QKV_N];
__device__ float g_QKV[(size_t)BT * QKV_N];                 // [bt][n]  37.7 MB
__device__ float g_Q[(size_t)BH * SEQ * D_HEAD];            // [bh][t][d]
__device__ float g_K[(size_t)BH * SEQ * D_HEAD];
__device__ float g_V[(size_t)BH * SEQ * D_HEAD];
__device__ float g_O[(size_t)BT * D_MODEL];                 // [bt][h*64+d]

// ---------------- 1. pack QKV weights into row-major [768, 2304] ------------
__global__ void pack_kernel(const float* __restrict__ Wq, const float* __restrict__ Wk,
                            const float* __restrict__ Wv, const float* __restrict__ bq,
                            const float* __restrict__ bk, const float* __restrict__ bv) {
    int idx = blockIdx.x * blockDim.x + threadIdx.x;
    if (idx >= 3 * N_HEADS * D_MODEL * D_HEAD) return;
    int d   = idx & 63;
    int c   = (idx >> 6) % D_MODEL;
    int hm  = (idx >> 6) / D_MODEL;    // mat*12 + h
    int h   = hm % N_HEADS;
    int mat = hm / N_HEADS;
    const float* W = (mat == 0) ? Wq : (mat == 1 ? Wk : Wv);
    float v = W[((size_t)h * D_MODEL + c) * D_HEAD + d];
    int n = mat * (N_HEADS * D_HEAD) + h * D_HEAD + d;
    g_Wpack[(size_t)c * QKV_N + n] = v;
    if (c == 0) {
        const float* bb = (mat == 0) ? bq : (mat == 1 ? bk : bv);
        g_bpack[n] = bb[h * D_HEAD + d];
    }
}

// ---------------- 2. generic SGEMM: C[M,N] = A[M,K] * B[K,N] (+bias) --------
// 128x128 tile, BK=16, 256 threads, 8x8 microtile, scalar FFMA.
__global__ __launch_bounds__(256)
void sgemm_kernel(const float* __restrict__ A, const float* __restrict__ Bm,
                  const float* __restrict__ bias, float* __restrict__ C,
                  int N, int K) {
    __shared__ __align__(16) float As[16 * 132];   // [k][m], padded
    __shared__ __align__(16) float Bs[16 * 132];   // [k][n], padded
    int tid = threadIdx.x;
    int bm = blockIdx.y * 128, bn = blockIdx.x * 128;
    int tr = tid >> 4, tc = tid & 15;

    float acc[8][8];
#pragma unroll
    for (int i = 0; i < 8; i++)
#pragma unroll
        for (int j = 0; j < 8; j++) acc[i][j] = 0.f;

    for (int kb = 0; kb < K; kb += 16) {
#pragma unroll
        for (int l = 0; l < 2; l++) {
            int f = tid + l * 256;
            int arow = f >> 2, akq = (f & 3) << 2;
            float4 av = *(const float4*)&A[(size_t)(bm + arow) * K + kb + akq];
            As[(akq + 0) * 132 + arow] = av.x;
            As[(akq + 1) * 132 + arow] = av.y;
            As[(akq + 2) * 132 + arow] = av.z;
            As[(akq + 3) * 132 + arow] = av.w;
            int bkr = f >> 5, bnq = (f & 31) << 2;
            *(float4*)&Bs[bkr * 132 + bnq] =
                *(const float4*)&Bm[(size_t)(kb + bkr) * N + bn + bnq];
        }
        __syncthreads();
#pragma unroll
        for (int k = 0; k < 16; k++) {
            float a[8], b[8];
            *(float4*)&a[0] = *(float4*)&As[k * 132 + tr * 8];
            *(float4*)&a[4] = *(float4*)&As[k * 132 + tr * 8 + 4];
            *(float4*)&b[0] = *(float4*)&Bs[k * 132 + tc * 8];
            *(float4*)&b[4] = *(float4*)&Bs[k * 132 + tc * 8 + 4];
#pragma unroll
            for (int i = 0; i < 8; i++)
#pragma unroll
                for (int j = 0; j < 8; j++)
                    acc[i][j] = fmaf(a[i], b[j], acc[i][j]);
        }
        __syncthreads();
    }

#pragma unroll
    for (int i = 0; i < 8; i++) {
        int row = bm + tr * 8 + i;
#pragma unroll
        for (int jq = 0; jq < 8; jq += 4) {
            int col = bn + tc * 8 + jq;
            float4 o;
            o.x = acc[i][jq + 0]; o.y = acc[i][jq + 1];
            o.z = acc[i][jq + 2]; o.w = acc[i][jq + 3];
            if (bias) {
                o.x += bias[col + 0]; o.y += bias[col + 1];
                o.z += bias[col + 2]; o.w += bias[col + 3];
            }
            *(float4*)&C[(size_t)row * N + col] = o;
        }
    }
}

// ---------------- 3. bias + RoPE + split into [BH, T, D] --------------------
__global__ void rope_split_kernel() {
    int idx = blockIdx.x * blockDim.x + threadIdx.x;
    if (idx >= BATCH * SEQ * N_HEADS * 32) return;
    int i = idx & 31;
    int h = (idx >> 5) % N_HEADS;
    int t = ((idx >> 5) / N_HEADS) % SEQ;
    int b = (idx >> 5) / N_HEADS / SEQ;
    size_t base = (size_t)(b * SEQ + t) * QKV_N;
    int hd = h * D_HEAD + 2 * i;

    float qr = g_QKV[base + hd]              + g_bpack[hd];
    float qi = g_QKV[base + hd + 1]          + g_bpack[hd + 1];
    float kr = g_QKV[base + 768 + hd]        + g_bpack[768 + hd];
    float ki = g_QKV[base + 768 + hd + 1]    + g_bpack[768 + hd + 1];
    float vr = g_QKV[base + 1536 + hd]       + g_bpack[1536 + hd];
    float vi = g_QKV[base + 1536 + hd + 1]   + g_bpack[1536 + hd + 1];

    float inv = powf(10000.0f, -(float)i * (1.0f / 32.0f));
    float ang = (float)t * inv;
    float sn, cs;
    sincosf(ang, &sn, &cs);

    size_t o = ((size_t)(b * N_HEADS + h) * SEQ + t) * D_HEAD + 2 * i;
    g_Q[o]     = qr * cs - qi * sn;
    g_Q[o + 1] = qr * sn + qi * cs;
    g_K[o]     = kr * cs - ki * sn;
    g_K[o + 1] = kr * sn + ki * cs;
    g_V[o]     = vr;
    g_V[o + 1] = vi;
}

// ---------------- 4. causal flash attention (static smem, <=48KB) -----------
// BM=64 q rows per CTA, BN=32 k cols per iter, 256 threads.
__global__ __launch_bounds__(256)
void attn_kernel() {
    __shared__ __align__(16) float Qs[64 * 65];   // [qrow][d]
    __shared__ __align__(16) float Ks[32 * 65];   // [kcol][d]
    __shared__ __align__(16) float Vs[32 * 68];   // [krow][d], stride 68 (16B)
    __shared__ __align__(16) float Ps[64 * 33];   // [qrow][k]

    int bh = blockIdx.y;
    int qb = gridDim.x - 1 - blockIdx.x;   // heavy q-blocks launch first
    int q0 = qb * 64;
    int tid = threadIdx.x;
    int tr = tid >> 4, tc = tid & 15;

    const float* Qg = g_Q + (size_t)bh * SEQ * D_HEAD;
    const float* Kg = g_K + (size_t)bh * SEQ * D_HEAD;
    const float* Vg = g_V + (size_t)bh * SEQ * D_HEAD;

    // load Q tile [64][64]
#pragma unroll
    for (int l = 0; l < 4; l++) {
        int f = tid + l * 256;
        int row = f >> 4;
        int dq = (f & 15) << 2;
        float4 v = *(const float4*)&Qg[(size_t)(q0 + row) * 64 + dq];
        float* p = &Qs[row * 65 + dq];
        p[0] = v.x; p[1] = v.y; p[2] = v.z; p[3] = v.w;
    }

    float m_i[4], l_i[4], acc[4][4];
#pragma unroll
    for (int i = 0; i < 4; i++) {
        m_i[i] = -INFINITY; l_i[i] = 0.f;
#pragma unroll
        for (int j = 0; j < 4; j++) acc[i][j] = 0.f;
    }

    int nkb = 2 * qb + 2;
    for (int kb = 0; kb < nkb; kb++) {
        int k0 = kb * 32;
        __syncthreads();
#pragma unroll
        for (int l = 0; l < 2; l++) {
            int f = tid + l * 256;
            int row = f >> 4;
            int dq = (f & 15) << 2;
            float4 kv = *(const float4*)&Kg[(size_t)(k0 + row) * 64 + dq];
            float* pk = &Ks[row * 65 + dq];
            pk[0] = kv.x; pk[1] = kv.y; pk[2] = kv.z; pk[3] = kv.w;
            float4 vv = *(const float4*)&Vg[(size_t)(k0 + row) * 64 + dq];
            *(float4*)&Vs[row * 68 + dq] = vv;
        }
        __syncthreads();

        // S = Q K^T  (4x2 per thread)
        float s[4][2];
#pragma unroll
        for (int i = 0; i < 4; i++) { s[i][0] = 0.f; s[i][1] = 0.f; }
#pragma unroll 8
        for (int d = 0; d < 64; d++) {
            float a[4], b[2];
#pragma unroll
            for (int i = 0; i < 4; i++) a[i] = Qs[(tr * 4 + i) * 65 + d];
            b[0] = Ks[(tc * 2 + 0) * 65 + d];
            b[1] = Ks[(tc * 2 + 1) * 65 + d];
#pragma unroll
            for (int i = 0; i < 4; i++) {
                s[i][0] = fmaf(a[i], b[0], s[i][0]);
                s[i][1] = fmaf(a[i], b[1], s[i][1]);
            }
        }

        // scale + causal mask
        bool diag = (k0 + 31 > q0);
#pragma unroll
        for (int i = 0; i < 4; i++)
#pragma unroll
            for (int j = 0; j < 2; j++) {
                float v = s[i][j] * 0.125f;
                if (diag && (k0 + tc * 2 + j > q0 + tr * 4 + i)) v = -1e30f;
                s[i][j] = v;
            }

        // online softmax (row reduce across the 16 tc lanes)
#pragma unroll
        for (int i = 0; i < 4; i++) {
            float mx = fmaxf(s[i][0], s[i][1]);
#pragma unroll
            for (int o = 8; o >= 1; o >>= 1)
                mx = fmaxf(mx, __shfl_xor_sync(0xffffffffu, mx, o));
            float mnew = fmaxf(m_i[i], mx);
            float alpha = __expf(m_i[i] - mnew);
            float p0 = __expf(s[i][0] - mnew);
            float p1 = __expf(s[i][1] - mnew);
            float rs = p0 + p1;
#pragma unroll
            for (int o = 8; o >= 1; o >>= 1)
                rs += __shfl_xor_sync(0xffffffffu, rs, o);
            m_i[i] = mnew;
            l_i[i] = l_i[i] * alpha + rs;
#pragma unroll
            for (int j = 0; j < 4; j++) acc[i][j] *= alpha;
            Ps[(tr * 4 + i) * 33 + tc * 2 + 0] = p0;
            Ps[(tr * 4 + i) * 33 + tc * 2 + 1] = p1;
        }
        __syncthreads();

        // O += P V   (4 rows x 4 d-cols per thread)
#pragma unroll 4
        for (int k = 0; k < 32; k++) {
            float4 vv = *(const float4*)&Vs[k * 68 + tc * 4];
            float p[4];
#pragma unroll
            for (int i = 0; i < 4; i++) p[i] = Ps[(tr * 4 + i) * 33 + k];
#pragma unroll
            for (int i = 0; i < 4; i++) {
                acc[i][0] = fmaf(p[i], vv.x, acc[i][0]);
                acc[i][1] = fmaf(p[i], vv.y, acc[i][1]);
                acc[i][2] = fmaf(p[i], vv.z, acc[i][2]);
                acc[i][3] = fmaf(p[i], vv.w, acc[i][3]);
            }
        }
    }

    // epilogue: normalize, write O in [bt][h*64+d] layout
    int b = bh / N_HEADS, h = bh % N_HEADS;
#pragma unroll
    for (int i = 0; i < 4; i++) {
        float r = 1.0f / l_i[i];
        float4 o4;
        o4.x = acc[i][0] * r; o4.y = acc[i][1] * r;
        o4.z = acc[i][2] * r; o4.w = acc[i][3] * r;
        int row = q0 + tr * 4 + i;
        *(float4*)&g_O[(size_t)(b * SEQ + row) * D_MODEL + h * D_HEAD + tc * 4] = o4;
    }
}

// ---------------- launch ----------------------------------------------------
extern "C" void kernel_launch(void* const* d_in, const int* in_sizes, int n_in,
                              void* d_out, int out_size) {
    // -------- robust input identification (host-side, capture-safe) --------
    const float *x, *Wq, *bq, *Wk, *bk, *Wv, *bv, *Wo, *bo;
    if (n_in >= 9 && in_sizes[0] == X_ELEMS) {
        // dict order: x, W_Q, b_Q, W_K, b_K, W_V, b_V, W_O, b_O
        x  = (const float*)d_in[0];
        Wq = (const float*)d_in[1]; bq = (const float*)d_in[2];
        Wk = (const float*)d_in[3]; bk = (const float*)d_in[4];
        Wv = (const float*)d_in[5]; bv = (const float*)d_in[6];
        Wo = (const float*)d_in[7]; bo = (const float*)d_in[8];
    } else if (n_in >= 9 && in_sizes[8] == X_ELEMS) {
        // sorted keys: W_K, W_O, W_Q, W_V, b_K, b_O, b_Q, b_V, x
        Wk = (const float*)d_in[0]; Wo = (const float*)d_in[1];
        Wq = (const float*)d_in[2]; Wv = (const float*)d_in[3];
        bk = (const float*)d_in[4]; bo = (const float*)d_in[5];
        bq = (const float*)d_in[6]; bv = (const float*)d_in[7];
        x  = (const float*)d_in[8];
    } else {
        const float* ws[4]; const float* bs[4];
        int nw = 0, nb = 0;
        x = (const float*)d_in[0];
        for (int i = 0; i < n_in; i++) {
            if (in_sizes[i] == X_ELEMS) x = (const float*)d_in[i];
            else if (in_sizes[i] == W_ELEMS && nw < 4) ws[nw++] = (const float*)d_in[i];
            else if (in_sizes[i] == B_ELEMS && nb < 4) bs[nb++] = (const float*)d_in[i];
        }
        Wq = ws[0]; Wk = ws[1]; Wv = ws[2]; Wo = ws[3];
        bq = bs[0]; bk = bs[1]; bv = bs[2]; bo = bs[3];
    }
    float* out = (float*)d_out;

    // -------- CRITICAL FIX: device addresses of __device__ globals ---------
    // Taking &g_X in host code yields the host shadow symbol, NOT the device
    // address. Must resolve via cudaGetSymbolAddress (host query; not a stream
    // op, so graph-capture-safe; no allocation).
    float *wpack_p = nullptr, *qkv_p = nullptr, *o_p = nullptr;
    cudaGetSymbolAddress((void**)&wpack_p, g_Wpack);
    cudaGetSymbolAddress((void**)&qkv_p,  g_QKV);
    cudaGetSymbolAddress((void**)&o_p,    g_O);

    // 1. pack weights/biases
    {
        int total = 3 * N_HEADS * D_MODEL * D_HEAD;
        pack_kernel<<<(total + 255) / 256, 256>>>(Wq, Wk, Wv, bq, bk, bv);
    }
    // 2. QKV projection: [4096,768] x [768,2304]
    {
        dim3 grid(QKV_N / 128, BT / 128);
        sgemm_kernel<<<grid, 256>>>(x, wpack_p, nullptr, qkv_p, QKV_N, D_MODEL);
    }
    // 3. bias + RoPE + relayout
    {
        int total = BATCH * SEQ * N_HEADS * 32;
        rope_split_kernel<<<total / 256, 256>>>();
    }
    // 4. causal flash attention
    {
        dim3 grid(SEQ / 64, BH);
        attn_kernel<<<grid, 256>>>();
    }
    // 5. output projection: [4096,768] x [768,768] + b_O
    {
        dim3 grid(D_MODEL / 128, BT / 128);
        sgemm_kernel<<<grid, 256>>>(o_p, Wo, bo, out, D_MODEL, D_MODEL);
    }
}

// round 10
// speedup vs baseline: 1.1515x; 1.1515x over previous
#include <cuda_runtime.h>
#include <math.h>
#include <stdint.h>

#define D_MODEL 768
#define N_HEADS 12
#define D_HEAD  64
#define BATCH   2
#define SEQ     2048
#define BT      (BATCH*SEQ)            // 4096
#define QKV_N   (3*N_HEADS*D_HEAD)     // 2304
#define BH      (BATCH*N_HEADS)        // 24

#define X_ELEMS  (BATCH*SEQ*D_MODEL)           // 3145728 (unique)
#define W_ELEMS  (N_HEADS*D_MODEL*D_HEAD)      // 589824  (x4)
#define B_ELEMS  (D_MODEL)                     // 768     (x4)

typedef unsigned long long ull;

// ---------------- f32x2 packed-math helpers (sm_100+) -----------------------
__device__ __forceinline__ ull pack2(float lo, float hi) {
    ull r;
    asm("mov.b64 %0, {%1, %2};" : "=l"(r) : "f"(lo), "f"(hi));
    return r;
}
__device__ __forceinline__ float2 unpack2(ull v) {
    float2 f;
    asm("mov.b64 {%0, %1}, %2;" : "=f"(f.x), "=f"(f.y) : "l"(v));
    return f;
}
__device__ __forceinline__ ull fma2(ull a, ull b, ull c) {
    ull d;
    asm("fma.rn.f32x2 %0, %1, %2, %3;" : "=l"(d) : "l"(a), "l"(b), "l"(c));
    return d;
}
__device__ __forceinline__ ull mul2(ull a, ull b) {
    ull d;
    asm("mul.rn.f32x2 %0, %1, %2;" : "=l"(d) : "l"(a), "l"(b));
    return d;
}

union F4U2 { float4 f; ull u[2]; };

// ---------------- scratch (static device globals) ---------------------------
__device__ float g_Wpack[(size_t)D_MODEL * QKV_N];
__device__ float g_bpack[QKV_N];
__device__ float g_QKV[(size_t)BT * QKV_N];
__device__ float g_Q[(size_t)BH * SEQ * D_HEAD];
__device__ float g_K[(size_t)BH * SEQ * D_HEAD];
__device__ float g_V[(size_t)BH * SEQ * D_HEAD];
__device__ float g_O[(size_t)BT * D_MODEL];

// ---------------- 1. pack QKV weights into row-major [768, 2304] ------------
__global__ void pack_kernel(const float* __restrict__ Wq, const float* __restrict__ Wk,
                            const float* __restrict__ Wv, const float* __restrict__ bq,
                            const float* __restrict__ bk, const float* __restrict__ bv) {
    int idx = blockIdx.x * blockDim.x + threadIdx.x;
    if (idx >= 3 * N_HEADS * D_MODEL * D_HEAD) return;
    int d   = idx & 63;
    int c   = (idx >> 6) % D_MODEL;
    int hm  = (idx >> 6) / D_MODEL;
    int h   = hm % N_HEADS;
    int mat = hm / N_HEADS;
    const float* W = (mat == 0) ? Wq : (mat == 1 ? Wk : Wv);
    float v = W[((size_t)h * D_MODEL + c) * D_HEAD + d];
    int n = mat * (N_HEADS * D_HEAD) + h * D_HEAD + d;
    g_Wpack[(size_t)c * QKV_N + n] = v;
    if (c == 0) {
        const float* bb = (mat == 0) ? bq : (mat == 1 ? bk : bv);
        g_bpack[n] = bb[h * D_HEAD + d];
    }
}

// ---------------- 2. SGEMM f32x2: C[M,N] = A[M,K]*B[K,N] (+bias) ------------
// 128x128 tile, BK=16, 256 threads, 8x8 microtile via split groups
// rows {tr*4..+3, 64+tr*4..+3}, cols {tc*4..+3, 64+tc*4..+3}.
__global__ __launch_bounds__(256)
void sgemm_kernel(const float* __restrict__ A, const float* __restrict__ Bm,
                  const float* __restrict__ bias, float* __restrict__ C,
                  int N, int K) {
    __shared__ __align__(16) float As[16 * 132];   // [k][m]
    __shared__ __align__(16) float Bs[16 * 132];   // [k][n]
    int tid = threadIdx.x;
    int bm = blockIdx.y * 128, bn = blockIdx.x * 128;
    int tr = tid >> 4, tc = tid & 15;

    ull acc2[8][4];
#pragma unroll
    for (int i = 0; i < 8; i++)
#pragma unroll
        for (int j = 0; j < 4; j++) acc2[i][j] = 0ull;

    for (int kb = 0; kb < K; kb += 16) {
#pragma unroll
        for (int l = 0; l < 2; l++) {
            int f = tid + l * 256;
            int arow = f >> 2, akq = (f & 3) << 2;
            float4 av = *(const float4*)&A[(size_t)(bm + arow) * K + kb + akq];
            As[(akq + 0) * 132 + arow] = av.x;
            As[(akq + 1) * 132 + arow] = av.y;
            As[(akq + 2) * 132 + arow] = av.z;
            As[(akq + 3) * 132 + arow] = av.w;
            int bkr = f >> 5, bnq = (f & 31) << 2;
            *(float4*)&Bs[bkr * 132 + bnq] =
                *(const float4*)&Bm[(size_t)(kb + bkr) * N + bn + bnq];
        }
        __syncthreads();
#pragma unroll
        for (int k = 0; k < 16; k++) {
            float a[8];
            *(float4*)&a[0] = *(float4*)&As[k * 132 + tr * 4];          // rows g0
            *(float4*)&a[4] = *(float4*)&As[k * 132 + 64 + tr * 4];     // rows g1
            F4U2 b0, b1;
            b0.f = *(const float4*)&Bs[k * 132 + tc * 4];               // cols g0
            b1.f = *(const float4*)&Bs[k * 132 + 64 + tc * 4];          // cols g1
#pragma unroll
            for (int i = 0; i < 8; i++) {
                ull aa = pack2(a[i], a[i]);
                acc2[i][0] = fma2(aa, b0.u[0], acc2[i][0]);
                acc2[i][1] = fma2(aa, b0.u[1], acc2[i][1]);
                acc2[i][2] = fma2(aa, b1.u[0], acc2[i][2]);
                acc2[i][3] = fma2(aa, b1.u[1], acc2[i][3]);
            }
        }
        __syncthreads();
    }

#pragma unroll
    for (int i = 0; i < 8; i++) {
        int row = bm + ((i >= 4) ? 64 : 0) + tr * 4 + (i & 3);
#pragma unroll
        for (int cg = 0; cg < 2; cg++) {
            int col = bn + cg * 64 + tc * 4;
            float2 p0 = unpack2(acc2[i][cg * 2 + 0]);
            float2 p1 = unpack2(acc2[i][cg * 2 + 1]);
            float4 o;
            o.x = p0.x; o.y = p0.y; o.z = p1.x; o.w = p1.y;
            if (bias) {
                o.x += bias[col + 0]; o.y += bias[col + 1];
                o.z += bias[col + 2]; o.w += bias[col + 3];
            }
            *(float4*)&C[(size_t)row * N + col] = o;
        }
    }
}

// ---------------- 3. bias + RoPE + split into [BH, T, D] --------------------
__global__ void rope_split_kernel() {
    int idx = blockIdx.x * blockDim.x + threadIdx.x;
    if (idx >= BATCH * SEQ * N_HEADS * 32) return;
    int i = idx & 31;
    int h = (idx >> 5) % N_HEADS;
    int t = ((idx >> 5) / N_HEADS) % SEQ;
    int b = (idx >> 5) / N_HEADS / SEQ;
    size_t base = (size_t)(b * SEQ + t) * QKV_N;
    int hd = h * D_HEAD + 2 * i;

    float qr = g_QKV[base + hd]              + g_bpack[hd];
    float qi = g_QKV[base + hd + 1]          + g_bpack[hd + 1];
    float kr = g_QKV[base + 768 + hd]        + g_bpack[768 + hd];
    float ki = g_QKV[base + 768 + hd + 1]    + g_bpack[768 + hd + 1];
    float vr = g_QKV[base + 1536 + hd]       + g_bpack[1536 + hd];
    float vi = g_QKV[base + 1536 + hd + 1]   + g_bpack[1536 + hd + 1];

    float inv = powf(10000.0f, -(float)i * (1.0f / 32.0f));
    float ang = (float)t * inv;
    float sn, cs;
    sincosf(ang, &sn, &cs);

    size_t o = ((size_t)(b * N_HEADS + h) * SEQ + t) * D_HEAD + 2 * i;
    g_Q[o]     = qr * cs - qi * sn;
    g_Q[o + 1] = qr * sn + qi * cs;
    g_K[o]     = kr * cs - ki * sn;
    g_K[o + 1] = kr * sn + ki * cs;
    g_V[o]     = vr;
    g_V[o + 1] = vi;
}

// ---------------- 4. causal flash attention, f32x2 --------------------------
// BM=128 q rows, BN=64 k cols per iter, 256 threads, 8x4 microtile.
// K stored transposed (Kt[d][col]) for conflict-free LDS.128 j-pair operands.
#define QS_STRIDE 68
#define KT_STRIDE 68
#define VS_STRIDE 68
#define PS_STRIDE 68
#define ATT_SMEM_FLOATS (128*QS_STRIDE + 64*KT_STRIDE + 64*VS_STRIDE + 128*PS_STRIDE)

__global__ __launch_bounds__(256)
void attn_kernel() {
    extern __shared__ __align__(16) float sm[];
    float* Qs = sm;                        // [128][68]  (row, d)
    float* Kt = Qs + 128 * QS_STRIDE;      // [64][68]   (d, col)  TRANSPOSED
    float* Vs = Kt + 64 * KT_STRIDE;       // [64][68]   (k, d)
    float* Ps = Vs + 64 * VS_STRIDE;       // [128][68]  (row, k)

    int bh = blockIdx.y;
    int qb = gridDim.x - 1 - blockIdx.x;   // heavy q-blocks first
    int q0 = qb * 128;
    int tid = threadIdx.x;
    int tr = tid >> 4, tc = tid & 15;      // rows tr*8+i ; cols tc*4+j

    const float* Qg = g_Q + (size_t)bh * SEQ * D_HEAD;
    const float* Kg = g_K + (size_t)bh * SEQ * D_HEAD;
    const float* Vg = g_V + (size_t)bh * SEQ * D_HEAD;

    // load Q tile [128][64]
#pragma unroll
    for (int l = 0; l < 8; l++) {
        int f = tid + l * 256;
        int row = f >> 4;
        int dq = (f & 15) << 2;
        float4 v = *(const float4*)&Qg[(size_t)(q0 + row) * 64 + dq];
        *(float4*)&Qs[row * QS_STRIDE + dq] = v;
    }

    float m_i[8], l_i[8];
    ull acc2[8][2];                        // O accum, pairs over d-cols
#pragma unroll
    for (int i = 0; i < 8; i++) {
        m_i[i] = -INFINITY; l_i[i] = 0.f;
        acc2[i][0] = 0ull; acc2[i][1] = 0ull;
    }

    int nkb = 2 * qb + 2;
    for (int kb = 0; kb < nkb; kb++) {
        int k0 = kb * 64;
        __syncthreads();
        // load K (transposed into Kt) and V tiles [64][64]
#pragma unroll
        for (int l = 0; l < 4; l++) {
            int f = tid + l * 256;
            int row = f >> 4;
            int dq = (f & 15) << 2;
            float4 kv = *(const float4*)&Kg[(size_t)(k0 + row) * 64 + dq];
            Kt[(dq + 0) * KT_STRIDE + row] = kv.x;
            Kt[(dq + 1) * KT_STRIDE + row] = kv.y;
            Kt[(dq + 2) * KT_STRIDE + row] = kv.z;
            Kt[(dq + 3) * KT_STRIDE + row] = kv.w;
            float4 vv = *(const float4*)&Vg[(size_t)(k0 + row) * 64 + dq];
            *(float4*)&Vs[row * VS_STRIDE + dq] = vv;
        }
        __syncthreads();

        // S = Q K^T : s2[i] pairs over j (cols tc*4+{0,1},{2,3})
        ull s2[8][2];
#pragma unroll
        for (int i = 0; i < 8; i++) { s2[i][0] = 0ull; s2[i][1] = 0ull; }
#pragma unroll 2
        for (int d = 0; d < 64; d += 2) {
            F4U2 kt0, kt1;
            kt0.f = *(const float4*)&Kt[d * KT_STRIDE + tc * 4];
            kt1.f = *(const float4*)&Kt[(d + 1) * KT_STRIDE + tc * 4];
#pragma unroll
            for (int i = 0; i < 8; i++) {
                float2 qf = unpack2(*(const ull*)&Qs[(tr * 8 + i) * QS_STRIDE + d]);
                ull qd0 = pack2(qf.x, qf.x);
                ull qd1 = pack2(qf.y, qf.y);
                s2[i][0] = fma2(qd0, kt0.u[0], s2[i][0]);
                s2[i][1] = fma2(qd0, kt0.u[1], s2[i][1]);
                s2[i][0] = fma2(qd1, kt1.u[0], s2[i][0]);
                s2[i][1] = fma2(qd1, kt1.u[1], s2[i][1]);
            }
        }

        // unpack, scale, causal mask
        float s[8][4];
#pragma unroll
        for (int i = 0; i < 8; i++) {
            float2 f0 = unpack2(s2[i][0]);
            float2 f1 = unpack2(s2[i][1]);
            s[i][0] = f0.x; s[i][1] = f0.y; s[i][2] = f1.x; s[i][3] = f1.y;
        }
        bool diag = (k0 + 63 > q0);
#pragma unroll
        for (int i = 0; i < 8; i++)
#pragma unroll
            for (int j = 0; j < 4; j++) {
                float v = s[i][j] * 0.125f;
                if (diag && (k0 + tc * 4 + j > q0 + tr * 8 + i)) v = -1e30f;
                s[i][j] = v;
            }

        // online softmax (row reduce across 16 tc lanes)
#pragma unroll
        for (int i = 0; i < 8; i++) {
            float mx = fmaxf(fmaxf(s[i][0], s[i][1]), fmaxf(s[i][2], s[i][3]));
#pragma unroll
            for (int o = 8; o >= 1; o >>= 1)
                mx = fmaxf(mx, __shfl_xor_sync(0xffffffffu, mx, o));
            float mnew = fmaxf(m_i[i], mx);
            float alpha = __expf(m_i[i] - mnew);
            float p0 = __expf(s[i][0] - mnew);
            float p1 = __expf(s[i][1] - mnew);
            float p2 = __expf(s[i][2] - mnew);
            float p3 = __expf(s[i][3] - mnew);
            float rs = (p0 + p1) + (p2 + p3);
#pragma unroll
            for (int o = 8; o >= 1; o >>= 1)
                rs += __shfl_xor_sync(0xffffffffu, rs, o);
            m_i[i] = mnew;
            l_i[i] = l_i[i] * alpha + rs;
            ull alpha2 = pack2(alpha, alpha);
            acc2[i][0] = mul2(acc2[i][0], alpha2);
            acc2[i][1] = mul2(acc2[i][1], alpha2);
            float4 pv; pv.x = p0; pv.y = p1; pv.z = p2; pv.w = p3;
            *(float4*)&Ps[(tr * 8 + i) * PS_STRIDE + tc * 4] = pv;
        }
        __syncthreads();

        // O += P V  (acc pairs over d; V row LDS.128 conflict-free)
#pragma unroll 4
        for (int k = 0; k < 64; k++) {
            F4U2 v;
            v.f = *(const float4*)&Vs[k * VS_STRIDE + tc * 4];
#pragma unroll
            for (int i = 0; i < 8; i++) {
                float pf = Ps[(tr * 8 + i) * PS_STRIDE + k];
                ull p2 = pack2(pf, pf);
                acc2[i][0] = fma2(p2, v.u[0], acc2[i][0]);
                acc2[i][1] = fma2(p2, v.u[1], acc2[i][1]);
            }
        }
    }

    // epilogue: normalize, write O in [bt][h*64+d] layout
    int b = bh / N_HEADS, h = bh % N_HEADS;
#pragma unroll
    for (int i = 0; i < 8; i++) {
        float r = 1.0f / l_i[i];
        float2 p0 = unpack2(acc2[i][0]);
        float2 p1 = unpack2(acc2[i][1]);
        float4 o4;
        o4.x = p0.x * r; o4.y = p0.y * r;
        o4.z = p1.x * r; o4.w = p1.y * r;
        int row = q0 + tr * 8 + i;
        *(float4*)&g_O[(size_t)(b * SEQ + row) * D_MODEL + h * D_HEAD + tc * 4] = o4;
    }
}

// ---------------- launch ----------------------------------------------------
extern "C" void kernel_launch(void* const* d_in, const int* in_sizes, int n_in,
                              void* d_out, int out_size) {
    const float *x, *Wq, *bq, *Wk, *bk, *Wv, *bv, *Wo, *bo;
    if (n_in >= 9 && in_sizes[0] == X_ELEMS) {
        x  = (const float*)d_in[0];
        Wq = (const float*)d_in[1]; bq = (const float*)d_in[2];
        Wk = (const float*)d_in[3]; bk = (const float*)d_in[4];
        Wv = (const float*)d_in[5]; bv = (const float*)d_in[6];
        Wo = (const float*)d_in[7]; bo = (const float*)d_in[8];
    } else if (n_in >= 9 && in_sizes[8] == X_ELEMS) {
        Wk = (const float*)d_in[0]; Wo = (const float*)d_in[1];
        Wq = (const float*)d_in[2]; Wv = (const float*)d_in[3];
        bk = (const float*)d_in[4]; bo = (const float*)d_in[5];
        bq = (const float*)d_in[6]; bv = (const float*)d_in[7];
        x  = (const float*)d_in[8];
    } else {
        const float* ws[4]; const float* bs[4];
        int nw = 0, nb = 0;
        x = (const float*)d_in[0];
        for (int i = 0; i < n_in; i++) {
            if (in_sizes[i] == X_ELEMS) x = (const float*)d_in[i];
            else if (in_sizes[i] == W_ELEMS && nw < 4) ws[nw++] = (const float*)d_in[i];
            else if (in_sizes[i] == B_ELEMS && nb < 4) bs[nb++] = (const float*)d_in[i];
        }
        Wq = ws[0]; Wk = ws[1]; Wv = ws[2]; Wo = ws[3];
        bq = bs[0]; bk = bs[1]; bv = bs[2]; bo = bs[3];
    }
    float* out = (float*)d_out;

    // device addresses of __device__ globals (host shadow symbols are wrong)
    float *wpack_p = nullptr, *qkv_p = nullptr, *o_p = nullptr;
    cudaGetSymbolAddress((void**)&wpack_p, g_Wpack);
    cudaGetSymbolAddress((void**)&qkv_p,  g_QKV);
    cudaGetSymbolAddress((void**)&o_p,    g_O);

    // dynamic smem opt-in for attention (idempotent host call, capture-safe)
    cudaFuncSetAttribute(attn_kernel, cudaFuncAttributeMaxDynamicSharedMemorySize,
                         ATT_SMEM_FLOATS * (int)sizeof(float));

    // 1. pack weights/biases
    {
        int total = 3 * N_HEADS * D_MODEL * D_HEAD;
        pack_kernel<<<(total + 255) / 256, 256>>>(Wq, Wk, Wv, bq, bk, bv);
    }
    // 2. QKV projection: [4096,768] x [768,2304]
    {
        dim3 grid(QKV_N / 128, BT / 128);
        sgemm_kernel<<<grid, 256>>>(x, wpack_p, nullptr, qkv_p, QKV_N, D_MODEL);
    }
    // 3. bias + RoPE + relayout
    {
        int total = BATCH * SEQ * N_HEADS * 32;
        rope_split_kernel<<<total / 256, 256>>>();
    }
    // 4. causal flash attention
    {
        dim3 grid(SEQ / 128, BH);
        attn_kernel<<<grid, 256, ATT_SMEM_FLOATS * (int)sizeof(float)>>>();
    }
    // 5. output projection: [4096,768] x [768,768] + b_O
    {
        dim3 grid(D_MODEL / 128, BT / 128);
        sgemm_kernel<<<grid, 256>>>(o_p, Wo, bo, out, D_MODEL, D_MODEL);
    }
}